// round 4
// baseline (speedup 1.0000x reference)
#include <cuda_runtime.h>
#include <cuda_bf16.h>

#define GSZ 8
#define DIMN 160
#define N3 (DIMN*DIMN*DIMN)

__device__ __forceinline__ float reflectf(float c) {
    // mirror about edge samples, period 2*(n-1) = 318, n-1 = 159
    c = fabsf(c);
    c = fmodf(c, 318.0f);
    if (c > 159.0f) c = 318.0f - c;
    return c;
}

__global__ void __launch_bounds__(256) elastic_kernel(
    const float* __restrict__ x,       // [B,2,160,160,160]
    const float* __restrict__ flow,    // [B,3,8,8,8]
    float* __restrict__ out)           // [B,2,160,160,160]
{
    __shared__ float sf[3 * GSZ * GSZ * GSZ];   // 6 KB coarse flow for this batch

    const int b = blockIdx.y;
    const float* fb = flow + (size_t)b * 3 * GSZ * GSZ * GSZ;
    for (int i = threadIdx.x; i < 3 * GSZ * GSZ * GSZ; i += blockDim.x)
        sf[i] = fb[i];
    __syncthreads();

    const int spatial = blockIdx.x * blockDim.x + threadIdx.x;  // 0 .. 160^3-1 exactly
    const int w = spatial % DIMN;
    const int t = spatial / DIMN;
    const int h = t % DIMN;
    const int d = t / DIMN;

    // ---- coarse flow upsample (trilinear, align_corners, clamp) ----
    const float s = 7.0f / 159.0f;
    const float cz = d * s, cy = h * s, cx = w * s;
    int iz0 = (int)cz, iy0 = (int)cy, ix0 = (int)cx;
    const float fz = cz - iz0, fy = cy - iy0, fx = cx - ix0;
    const int iz1 = min(iz0 + 1, GSZ - 1);
    const int iy1 = min(iy0 + 1, GSZ - 1);
    const int ix1 = min(ix0 + 1, GSZ - 1);

    const float gz0 = 1.0f - fz, gy0 = 1.0f - fy, gx0 = 1.0f - fx;
    float cw[8];
    cw[0] = gz0 * gy0 * gx0;  cw[1] = gz0 * gy0 * fx;
    cw[2] = gz0 * fy  * gx0;  cw[3] = gz0 * fy  * fx;
    cw[4] = fz  * gy0 * gx0;  cw[5] = fz  * gy0 * fx;
    cw[6] = fz  * fy  * gx0;  cw[7] = fz  * fy  * fx;

    int ci[8];
    ci[0] = (iz0 * GSZ + iy0) * GSZ + ix0;
    ci[1] = (iz0 * GSZ + iy0) * GSZ + ix1;
    ci[2] = (iz0 * GSZ + iy1) * GSZ + ix0;
    ci[3] = (iz0 * GSZ + iy1) * GSZ + ix1;
    ci[4] = (iz1 * GSZ + iy0) * GSZ + ix0;
    ci[5] = (iz1 * GSZ + iy0) * GSZ + ix1;
    ci[6] = (iz1 * GSZ + iy1) * GSZ + ix0;
    ci[7] = (iz1 * GSZ + iy1) * GSZ + ix1;

    float upx = 0.f, upy = 0.f, upz = 0.f;
    #pragma unroll
    for (int k = 0; k < 8; k++) {
        upx = fmaf(cw[k], sf[ci[k]],             upx);
        upy = fmaf(cw[k], sf[512 + ci[k]],       upy);
        upz = fmaf(cw[k], sf[1024 + ci[k]],      upz);
    }

    // ---- warp coordinate: i = voxel + up * (n-1)/2 ; mirror-reflect ----
    float px = reflectf((float)w + upx * 79.5f);
    float py = reflectf((float)h + upy * 79.5f);
    float pz = reflectf((float)d + upz * 79.5f);

    int jx0 = (int)px, jy0 = (int)py, jz0 = (int)pz;
    jx0 = min(jx0, DIMN - 1); jy0 = min(jy0, DIMN - 1); jz0 = min(jz0, DIMN - 1);
    const float ax = px - jx0, ay = py - jy0, az = pz - jz0;
    const int jx1 = min(jx0 + 1, DIMN - 1);
    const int jy1 = min(jy0 + 1, DIMN - 1);
    const int jz1 = min(jz0 + 1, DIMN - 1);

    const float bx0 = 1.0f - ax, by0 = 1.0f - ay, bz0 = 1.0f - az;
    float tw[8];
    tw[0] = bz0 * by0 * bx0;  tw[1] = bz0 * by0 * ax;
    tw[2] = bz0 * ay  * bx0;  tw[3] = bz0 * ay  * ax;
    tw[4] = az  * by0 * bx0;  tw[5] = az  * by0 * ax;
    tw[6] = az  * ay  * bx0;  tw[7] = az  * ay  * ax;

    int off[8];
    const int r00 = (jz0 * DIMN + jy0) * DIMN;
    const int r01 = (jz0 * DIMN + jy1) * DIMN;
    const int r10 = (jz1 * DIMN + jy0) * DIMN;
    const int r11 = (jz1 * DIMN + jy1) * DIMN;
    off[0] = r00 + jx0;  off[1] = r00 + jx1;
    off[2] = r01 + jx0;  off[3] = r01 + jx1;
    off[4] = r10 + jx0;  off[5] = r10 + jx1;
    off[6] = r11 + jx0;  off[7] = r11 + jx1;

    const float* __restrict__ x0 = x + (size_t)b * 2 * N3;       // channel 0
    const float* __restrict__ x1 = x0 + N3;                      // channel 1

    float v0 = 0.f, v1 = 0.f;
    #pragma unroll
    for (int k = 0; k < 8; k++) {
        v0 = fmaf(tw[k], __ldg(x0 + off[k]), v0);
        v1 = fmaf(tw[k], __ldg(x1 + off[k]), v1);
    }

    float* __restrict__ o0 = out + (size_t)b * 2 * N3;
    o0[spatial]      = v0;
    o0[N3 + spatial] = v1;
}

extern "C" void kernel_launch(void* const* d_in, const int* in_sizes, int n_in,
                              void* d_out, int out_size) {
    const float* x    = (const float*)d_in[0];
    const float* flow = (const float*)d_in[1];
    float* out        = (float*)d_out;

    dim3 block(256);
    dim3 grid(N3 / 256, 4);   // 160^3 = 4,096,000 divisible by 256 -> 16000 blocks per batch
    elastic_kernel<<<grid, block>>>(x, flow, out);
}

// round 5
// speedup vs baseline: 1.0002x; 1.0002x over previous
#include <cuda_runtime.h>
#include <cuda_bf16.h>

#define GSZ 8
#define DIMN 160
#define N3 (DIMN*DIMN*DIMN)

__device__ __forceinline__ float reflectf(float c) {
    // mirror about edge samples, period 2*(n-1) = 318, n-1 = 159
    c = fabsf(c);
    c = fmodf(c, 318.0f);
    if (c > 159.0f) c = 318.0f - c;
    return c;
}

__global__ void __launch_bounds__(256) elastic_kernel(
    const float* __restrict__ x,       // [B,2,160,160,160]
    const float* __restrict__ flow,    // [B,3,8,8,8]
    float* __restrict__ out)           // [B,2,160,160,160]
{
    __shared__ float sf[3 * GSZ * GSZ * GSZ];   // 6 KB coarse flow for this batch

    const int b = blockIdx.y;
    const float* fb = flow + (size_t)b * 3 * GSZ * GSZ * GSZ;
    for (int i = threadIdx.x; i < 3 * GSZ * GSZ * GSZ; i += blockDim.x)
        sf[i] = fb[i];
    __syncthreads();

    const int spatial = blockIdx.x * blockDim.x + threadIdx.x;  // 0 .. 160^3-1 exactly
    const int w = spatial % DIMN;
    const int t = spatial / DIMN;
    const int h = t % DIMN;
    const int d = t / DIMN;

    // ---- coarse flow upsample (trilinear, align_corners, clamp) ----
    const float s = 7.0f / 159.0f;
    const float cz = d * s, cy = h * s, cx = w * s;
    int iz0 = (int)cz, iy0 = (int)cy, ix0 = (int)cx;
    const float fz = cz - iz0, fy = cy - iy0, fx = cx - ix0;
    const int iz1 = min(iz0 + 1, GSZ - 1);
    const int iy1 = min(iy0 + 1, GSZ - 1);
    const int ix1 = min(ix0 + 1, GSZ - 1);

    const float gz0 = 1.0f - fz, gy0 = 1.0f - fy, gx0 = 1.0f - fx;
    float cw[8];
    cw[0] = gz0 * gy0 * gx0;  cw[1] = gz0 * gy0 * fx;
    cw[2] = gz0 * fy  * gx0;  cw[3] = gz0 * fy  * fx;
    cw[4] = fz  * gy0 * gx0;  cw[5] = fz  * gy0 * fx;
    cw[6] = fz  * fy  * gx0;  cw[7] = fz  * fy  * fx;

    int ci[8];
    ci[0] = (iz0 * GSZ + iy0) * GSZ + ix0;
    ci[1] = (iz0 * GSZ + iy0) * GSZ + ix1;
    ci[2] = (iz0 * GSZ + iy1) * GSZ + ix0;
    ci[3] = (iz0 * GSZ + iy1) * GSZ + ix1;
    ci[4] = (iz1 * GSZ + iy0) * GSZ + ix0;
    ci[5] = (iz1 * GSZ + iy0) * GSZ + ix1;
    ci[6] = (iz1 * GSZ + iy1) * GSZ + ix0;
    ci[7] = (iz1 * GSZ + iy1) * GSZ + ix1;

    float upx = 0.f, upy = 0.f, upz = 0.f;
    #pragma unroll
    for (int k = 0; k < 8; k++) {
        upx = fmaf(cw[k], sf[ci[k]],             upx);
        upy = fmaf(cw[k], sf[512 + ci[k]],       upy);
        upz = fmaf(cw[k], sf[1024 + ci[k]],      upz);
    }

    // ---- warp coordinate: i = voxel + up * (n-1)/2 ; mirror-reflect ----
    float px = reflectf((float)w + upx * 79.5f);
    float py = reflectf((float)h + upy * 79.5f);
    float pz = reflectf((float)d + upz * 79.5f);

    int jx0 = (int)px, jy0 = (int)py, jz0 = (int)pz;
    jx0 = min(jx0, DIMN - 1); jy0 = min(jy0, DIMN - 1); jz0 = min(jz0, DIMN - 1);
    const float ax = px - jx0, ay = py - jy0, az = pz - jz0;
    const int jx1 = min(jx0 + 1, DIMN - 1);
    const int jy1 = min(jy0 + 1, DIMN - 1);
    const int jz1 = min(jz0 + 1, DIMN - 1);

    const float bx0 = 1.0f - ax, by0 = 1.0f - ay, bz0 = 1.0f - az;
    float tw[8];
    tw[0] = bz0 * by0 * bx0;  tw[1] = bz0 * by0 * ax;
    tw[2] = bz0 * ay  * bx0;  tw[3] = bz0 * ay  * ax;
    tw[4] = az  * by0 * bx0;  tw[5] = az  * by0 * ax;
    tw[6] = az  * ay  * bx0;  tw[7] = az  * ay  * ax;

    int off[8];
    const int r00 = (jz0 * DIMN + jy0) * DIMN;
    const int r01 = (jz0 * DIMN + jy1) * DIMN;
    const int r10 = (jz1 * DIMN + jy0) * DIMN;
    const int r11 = (jz1 * DIMN + jy1) * DIMN;
    off[0] = r00 + jx0;  off[1] = r00 + jx1;
    off[2] = r01 + jx0;  off[3] = r01 + jx1;
    off[4] = r10 + jx0;  off[5] = r10 + jx1;
    off[6] = r11 + jx0;  off[7] = r11 + jx1;

    const float* __restrict__ x0 = x + (size_t)b * 2 * N3;       // channel 0
    const float* __restrict__ x1 = x0 + N3;                      // channel 1

    float v0 = 0.f, v1 = 0.f;
    #pragma unroll
    for (int k = 0; k < 8; k++) {
        v0 = fmaf(tw[k], __ldg(x0 + off[k]), v0);
        v1 = fmaf(tw[k], __ldg(x1 + off[k]), v1);
    }

    float* __restrict__ o0 = out + (size_t)b * 2 * N3;
    o0[spatial]      = v0;
    o0[N3 + spatial] = v1;
}

extern "C" void kernel_launch(void* const* d_in, const int* in_sizes, int n_in,
                              void* d_out, int out_size) {
    const float* x    = (const float*)d_in[0];
    const float* flow = (const float*)d_in[1];
    float* out        = (float*)d_out;

    dim3 block(256);
    dim3 grid(N3 / 256, 4);   // 160^3 = 4,096,000 divisible by 256 -> 16000 blocks per batch
    elastic_kernel<<<grid, block>>>(x, flow, out);
}

// round 6
// speedup vs baseline: 1.3736x; 1.3734x over previous
#include <cuda_runtime.h>
#include <cuda_bf16.h>

#define GSZ 8
#define DIMN 160
#define N3 (DIMN*DIMN*DIMN)

__device__ __forceinline__ float reflectf(float c) {
    // mirror about edge samples, period 2*(n-1)=318; valid for |c| < ~636
    c = fabsf(c);
    c = (c > 159.0f) ? (318.0f - c) : c;
    c = fabsf(c);
    c = (c > 159.0f) ? (318.0f - c) : c;
    return c;
}

__global__ void __launch_bounds__(DIMN) elastic_kernel(
    const float* __restrict__ x,       // [B,2,160,160,160]
    const float* __restrict__ flow,    // [B,3,8,8,8]
    float* __restrict__ out)           // [B,2,160,160,160]
{
    const int h = blockIdx.x;
    const int d = blockIdx.y;
    const int b = blockIdx.z;

    // ---- per-block: bilinear-(z,y) reduce coarse flow to 8 x-nodes ----
    __shared__ float g[3][GSZ];

    const float s = 7.0f / 159.0f;
    const float cz = d * s, cy = h * s;
    const int iz0 = (int)cz, iy0 = (int)cy;
    const float fz = cz - iz0, fy = cy - iy0;
    const int iz1 = min(iz0 + 1, GSZ - 1);
    const int iy1 = min(iy0 + 1, GSZ - 1);

    if (threadIdx.x < 3 * GSZ) {
        const int c  = threadIdx.x >> 3;     // component 0..2
        const int ix = threadIdx.x & 7;      // x-node 0..7
        const float* fb = flow + ((size_t)b * 3 + c) * (GSZ * GSZ * GSZ);
        const float v00 = fb[(iz0 * GSZ + iy0) * GSZ + ix];
        const float v01 = fb[(iz0 * GSZ + iy1) * GSZ + ix];
        const float v10 = fb[(iz1 * GSZ + iy0) * GSZ + ix];
        const float v11 = fb[(iz1 * GSZ + iy1) * GSZ + ix];
        const float v0 = v00 + fy * (v01 - v00);
        const float v1 = v10 + fy * (v11 - v10);
        g[c][ix] = v0 + fz * (v1 - v0);
    }
    __syncthreads();

    // ---- per-thread: finish upsample with 1-D lerp along x ----
    const int w = threadIdx.x;
    const float cx = w * s;
    const int ix0 = (int)cx;
    const float fx = cx - ix0;
    const int ix1 = min(ix0 + 1, GSZ - 1);

    const float g0a = g[0][ix0], g0b = g[0][ix1];
    const float g1a = g[1][ix0], g1b = g[1][ix1];
    const float g2a = g[2][ix0], g2b = g[2][ix1];
    const float upx = g0a + fx * (g0b - g0a);
    const float upy = g1a + fx * (g1b - g1a);
    const float upz = g2a + fx * (g2b - g2a);

    // ---- warp coordinate: voxel + up*(n-1)/2, mirror-reflect ----
    const float px = reflectf((float)w + upx * 79.5f);
    const float py = reflectf((float)h + upy * 79.5f);
    const float pz = reflectf((float)d + upz * 79.5f);

    int jx0 = min((int)px, DIMN - 1);
    int jy0 = min((int)py, DIMN - 1);
    int jz0 = min((int)pz, DIMN - 1);
    const float ax = px - jx0, ay = py - jy0, az = pz - jz0;
    const int jx1 = min(jx0 + 1, DIMN - 1);
    const int jy1 = min(jy0 + 1, DIMN - 1);
    const int jz1 = min(jz0 + 1, DIMN - 1);

    const float bx0 = 1.0f - ax, by0 = 1.0f - ay, bz0 = 1.0f - az;
    float tw[8];
    tw[0] = bz0 * by0 * bx0;  tw[1] = bz0 * by0 * ax;
    tw[2] = bz0 * ay  * bx0;  tw[3] = bz0 * ay  * ax;
    tw[4] = az  * by0 * bx0;  tw[5] = az  * by0 * ax;
    tw[6] = az  * ay  * bx0;  tw[7] = az  * ay  * ax;

    int off[8];
    const int r00 = (jz0 * DIMN + jy0) * DIMN;
    const int r01 = (jz0 * DIMN + jy1) * DIMN;
    const int r10 = (jz1 * DIMN + jy0) * DIMN;
    const int r11 = (jz1 * DIMN + jy1) * DIMN;
    off[0] = r00 + jx0;  off[1] = r00 + jx1;
    off[2] = r01 + jx0;  off[3] = r01 + jx1;
    off[4] = r10 + jx0;  off[5] = r10 + jx1;
    off[6] = r11 + jx0;  off[7] = r11 + jx1;

    const float* __restrict__ x0 = x + (size_t)b * 2 * N3;   // channel 0
    const float* __restrict__ x1 = x0 + N3;                  // channel 1

    // front-batch all 16 loads for max MLP
    float t0[8], t1[8];
    #pragma unroll
    for (int k = 0; k < 8; k++) t0[k] = __ldg(x0 + off[k]);
    #pragma unroll
    for (int k = 0; k < 8; k++) t1[k] = __ldg(x1 + off[k]);

    float v0 = 0.f, v1 = 0.f;
    #pragma unroll
    for (int k = 0; k < 8; k++) {
        v0 = fmaf(tw[k], t0[k], v0);
        v1 = fmaf(tw[k], t1[k], v1);
    }

    const int spatial = (d * DIMN + h) * DIMN + w;
    float* __restrict__ o0 = out + (size_t)b * 2 * N3;
    o0[spatial]      = v0;
    o0[N3 + spatial] = v1;
}

extern "C" void kernel_launch(void* const* d_in, const int* in_sizes, int n_in,
                              void* d_out, int out_size) {
    const float* x    = (const float*)d_in[0];
    const float* flow = (const float*)d_in[1];
    float* out        = (float*)d_out;

    dim3 block(DIMN);           // one w-line per block
    dim3 grid(DIMN, DIMN, 4);   // (h, d, b)
    elastic_kernel<<<grid, block>>>(x, flow, out);
}

// round 7
// speedup vs baseline: 1.3794x; 1.0042x over previous
#include <cuda_runtime.h>
#include <cuda_bf16.h>

#define GSZ 8
#define DIMN 160
#define N3 (DIMN*DIMN*DIMN)

__device__ __forceinline__ float reflect1(float c) {
    // mirror, period 2*(n-1)=318; single fold valid for c in [-318, 318+159]
    // here c = voxel + delta, delta bounded by ~ +/-15 -> c in [-15, 174]
    c = fabsf(c);
    return (c > 159.0f) ? (318.0f - c) : c;
}

__global__ void __launch_bounds__(256) elastic_kernel(
    const float* __restrict__ x,       // [B,2,160,160,160]
    const float* __restrict__ flow,    // [B,3,8,8,8]
    float* __restrict__ out)           // [B,2,160,160,160]
{
    // block: 32 w x 8 h ; grid: (5 w-tiles, 20 h-tiles * 160 d, 4 b)
    __shared__ float gh[8][24];        // [h_local][c*8 + x-node]

    const int b  = blockIdx.z;
    const int d  = blockIdx.y / 20;
    const int ht = blockIdx.y % 20;
    const int tx = threadIdx.x;
    const int ty = threadIdx.y;
    const int t  = ty * 32 + tx;

    const float s = 7.0f / 159.0f;
    const float cz = d * s;
    const int   iz0 = (int)cz;
    const float fz  = cz - iz0;
    const int   iz1 = min(iz0 + 1, GSZ - 1);

    // ---- stage: bilinear-(z,y) reduce coarse flow to 8 x-nodes, per h-line ----
    if (t < 192) {
        const int hl   = t / 24;           // h_local 0..7
        const int r    = t - hl * 24;      // 0..23
        const int c    = r >> 3;           // component
        const int node = r & 7;            // x-node
        const int hg   = ht * 8 + hl;
        const float cy = hg * s;
        const int   iy0 = (int)cy;
        const float fy  = cy - iy0;
        const int   iy1 = min(iy0 + 1, GSZ - 1);
        const float* fb = flow + (((size_t)b * 3 + c) << 9);  // *512
        const float v00 = fb[(iz0 * GSZ + iy0) * GSZ + node];
        const float v01 = fb[(iz0 * GSZ + iy1) * GSZ + node];
        const float v10 = fb[(iz1 * GSZ + iy0) * GSZ + node];
        const float v11 = fb[(iz1 * GSZ + iy1) * GSZ + node];
        const float v0 = v00 + fy * (v01 - v00);
        const float v1 = v10 + fy * (v11 - v10);
        gh[hl][r] = v0 + fz * (v1 - v0);
    }
    __syncthreads();

    const int w = blockIdx.x * 32 + tx;
    const int h = ht * 8 + ty;

    // ---- finish coarse upsample: 1-D lerp along x ----
    const float cx = w * s;
    const int   ix0 = (int)cx;
    const float fx  = cx - ix0;
    const int   ix1 = min(ix0 + 1, GSZ - 1);

    const float g0a = gh[ty][ix0],      g0b = gh[ty][ix1];
    const float g1a = gh[ty][8 + ix0],  g1b = gh[ty][8 + ix1];
    const float g2a = gh[ty][16 + ix0], g2b = gh[ty][16 + ix1];
    const float upx = g0a + fx * (g0b - g0a);
    const float upy = g1a + fx * (g1b - g1a);
    const float upz = g2a + fx * (g2b - g2a);

    // ---- warp coordinate: voxel + up*(n-1)/2, mirror-reflect (single fold) ----
    const float px = reflect1((float)w + upx * 79.5f);
    const float py = reflect1((float)h + upy * 79.5f);
    const float pz = reflect1((float)d + upz * 79.5f);

    // px,py,pz in [0,159] -> no clamp needed on the floor tap
    const int jx0 = (int)px;
    const int jy0 = (int)py;
    const int jz0 = (int)pz;
    const float ax = px - jx0, ay = py - jy0, az = pz - jz0;
    const int jx1 = min(jx0 + 1, DIMN - 1);
    const int jy1 = min(jy0 + 1, DIMN - 1);
    const int jz1 = min(jz0 + 1, DIMN - 1);

    // two-level weight factorization
    const float bx0 = 1.0f - ax, by0 = 1.0f - ay, bz0 = 1.0f - az;
    const float w00 = bz0 * by0, w01 = bz0 * ay;
    const float w10 = az * by0,  w11 = az * ay;
    float tw[8];
    tw[0] = w00 * bx0;  tw[1] = w00 * ax;
    tw[2] = w01 * bx0;  tw[3] = w01 * ax;
    tw[4] = w10 * bx0;  tw[5] = w10 * ax;
    tw[6] = w11 * bx0;  tw[7] = w11 * ax;

    int off[8];
    const int r00 = (jz0 * DIMN + jy0) * DIMN;
    const int r01 = (jz0 * DIMN + jy1) * DIMN;
    const int r10 = (jz1 * DIMN + jy0) * DIMN;
    const int r11 = (jz1 * DIMN + jy1) * DIMN;
    off[0] = r00 + jx0;  off[1] = r00 + jx1;
    off[2] = r01 + jx0;  off[3] = r01 + jx1;
    off[4] = r10 + jx0;  off[5] = r10 + jx1;
    off[6] = r11 + jx0;  off[7] = r11 + jx1;

    const float* __restrict__ x0 = x + (size_t)b * 2 * N3;   // channel 0
    const float* __restrict__ x1 = x0 + N3;                  // channel 1

    // front-batch all 16 loads for max MLP
    float t0[8], t1[8];
    #pragma unroll
    for (int k = 0; k < 8; k++) t0[k] = __ldg(x0 + off[k]);
    #pragma unroll
    for (int k = 0; k < 8; k++) t1[k] = __ldg(x1 + off[k]);

    float v0 = 0.f, v1 = 0.f;
    #pragma unroll
    for (int k = 0; k < 8; k++) {
        v0 = fmaf(tw[k], t0[k], v0);
        v1 = fmaf(tw[k], t1[k], v1);
    }

    const int spatial = (d * DIMN + h) * DIMN + w;
    float* __restrict__ o0 = out + (size_t)b * 2 * N3;
    o0[spatial]      = v0;
    o0[N3 + spatial] = v1;
}

extern "C" void kernel_launch(void* const* d_in, const int* in_sizes, int n_in,
                              void* d_out, int out_size) {
    const float* x    = (const float*)d_in[0];
    const float* flow = (const float*)d_in[1];
    float* out        = (float*)d_out;

    dim3 block(32, 8);                 // 256 threads: 32 w x 8 h
    dim3 grid(5, 20 * DIMN, 4);        // (w-tiles, h-tiles*d, b)
    elastic_kernel<<<grid, block>>>(x, flow, out);
}

// round 8
// speedup vs baseline: 1.3826x; 1.0023x over previous
#include <cuda_runtime.h>
#include <cuda_bf16.h>

#define GSZ 8
#define DIMN 160
#define N3 (DIMN*DIMN*DIMN)

__device__ __forceinline__ float reflect1(float c) {
    // mirror, period 2*(n-1)=318; single fold valid here since |delta| <= ~16
    c = fabsf(c);
    return (c > 159.0f) ? (318.0f - c) : c;
}

__global__ void __launch_bounds__(256) elastic_kernel(
    const float* __restrict__ x,       // [B,2,160,160,160]
    const float* __restrict__ flow,    // [B,3,8,8,8]
    float* __restrict__ out)           // [B,2,160,160,160]
{
    // block: 32 w x 8 h ; warp == one h-line. grid: (5 w-tiles, 20 h-tiles * 160 d, 4 b)
    const int b  = blockIdx.z;
    const int d  = blockIdx.y / 20;
    const int ht = blockIdx.y % 20;
    const int tx = threadIdx.x;        // lane
    const int ty = threadIdx.y;        // warp id == h_local

    const float s = 7.0f / 159.0f;
    const float cz = d * s;
    const int   iz0 = (int)cz;
    const float fz  = cz - iz0;
    const int   iz1 = min(iz0 + 1, GSZ - 1);

    const int h = ht * 8 + ty;
    const int w = blockIdx.x * 32 + tx;

    // ---- per-warp: lanes 0..23 reduce coarse flow bilinearly in (z,y) ----
    // lane l (<24): component c = l>>3, x-node = l&7 ; value kept in register,
    // distributed by shuffle. No smem, no block barrier.
    float gval;
    {
        const int  l    = min(tx, 23);
        const int  c    = l >> 3;
        const int  node = l & 7;
        const float cy  = h * s;
        const int   iy0 = (int)cy;
        const float fy  = cy - iy0;
        const int   iy1 = min(iy0 + 1, GSZ - 1);
        const float* fb = flow + (((size_t)b * 3 + c) << 9);   // *512
        const float v00 = __ldg(fb + (iz0 * GSZ + iy0) * GSZ + node);
        const float v01 = __ldg(fb + (iz0 * GSZ + iy1) * GSZ + node);
        const float v10 = __ldg(fb + (iz1 * GSZ + iy0) * GSZ + node);
        const float v11 = __ldg(fb + (iz1 * GSZ + iy1) * GSZ + node);
        const float v0 = v00 + fy * (v01 - v00);
        const float v1 = v10 + fy * (v11 - v10);
        gval = v0 + fz * (v1 - v0);
    }

    // ---- finish coarse upsample: 1-D lerp along x via shuffles ----
    const float cx = w * s;
    const int   ix0 = (int)cx;
    const float fx  = cx - ix0;
    const int   ix1 = min(ix0 + 1, GSZ - 1);

    const float g0a = __shfl_sync(0xffffffffu, gval, ix0);
    const float g0b = __shfl_sync(0xffffffffu, gval, ix1);
    const float g1a = __shfl_sync(0xffffffffu, gval, 8 + ix0);
    const float g1b = __shfl_sync(0xffffffffu, gval, 8 + ix1);
    const float g2a = __shfl_sync(0xffffffffu, gval, 16 + ix0);
    const float g2b = __shfl_sync(0xffffffffu, gval, 16 + ix1);
    const float upx = g0a + fx * (g0b - g0a);
    const float upy = g1a + fx * (g1b - g1a);
    const float upz = g2a + fx * (g2b - g2a);

    // ---- warp coordinate: voxel + up*(n-1)/2, mirror-reflect (single fold) ----
    const float px = reflect1((float)w + upx * 79.5f);
    const float py = reflect1((float)h + upy * 79.5f);
    const float pz = reflect1((float)d + upz * 79.5f);

    // px,py,pz in [0,159] -> floor tap needs no clamp
    const int jx0 = (int)px;
    const int jy0 = (int)py;
    const int jz0 = (int)pz;
    const float ax = px - (float)jx0;
    const float ay = py - (float)jy0;
    const float az = pz - (float)jz0;

    // incremental neighbor steps (0 at the top edge)
    const int dx = (jx0 < DIMN - 1) ? 1      : 0;
    const int dy = (jy0 < DIMN - 1) ? DIMN   : 0;
    const int dz = (jz0 < DIMN - 1) ? DIMN*DIMN : 0;

    // factorized weights
    const float bx0 = 1.0f - ax, by0 = 1.0f - ay, bz0 = 1.0f - az;
    const float w00 = bz0 * by0, w01 = bz0 * ay;
    const float w10 = az * by0,  w11 = az * ay;
    float tw[8];
    tw[0] = w00 * bx0;  tw[1] = w00 * ax;
    tw[2] = w01 * bx0;  tw[3] = w01 * ax;
    tw[4] = w10 * bx0;  tw[5] = w10 * ax;
    tw[6] = w11 * bx0;  tw[7] = w11 * ax;

    const int base = (jz0 * DIMN + jy0) * DIMN + jx0;
    int off[8];
    off[0] = base;          off[1] = base + dx;
    off[2] = off[0] + dy;   off[3] = off[2] + dx;
    off[4] = off[0] + dz;   off[5] = off[4] + dx;
    off[6] = off[4] + dy;   off[7] = off[6] + dx;

    const float* __restrict__ x0 = x + (size_t)b * 2 * N3;   // channel 0; +N3 = channel 1

    // front-batch all 16 loads; channel-1 address = channel-0 pointer + N3
    float t0[8], t1[8];
    #pragma unroll
    for (int k = 0; k < 8; k++) {
        const float* p = x0 + off[k];
        t0[k] = __ldg(p);
        t1[k] = __ldg(p + N3);
    }

    float v0 = 0.f, v1 = 0.f;
    #pragma unroll
    for (int k = 0; k < 8; k++) {
        v0 = fmaf(tw[k], t0[k], v0);
        v1 = fmaf(tw[k], t1[k], v1);
    }

    const int spatial = (d * DIMN + h) * DIMN + w;
    float* __restrict__ o0 = out + (size_t)b * 2 * N3;
    o0[spatial]      = v0;
    o0[N3 + spatial] = v1;
}

extern "C" void kernel_launch(void* const* d_in, const int* in_sizes, int n_in,
                              void* d_out, int out_size) {
    const float* x    = (const float*)d_in[0];
    const float* flow = (const float*)d_in[1];
    float* out        = (float*)d_out;

    dim3 block(32, 8);                 // 256 threads: 32 w x 8 h, warp == h-line
    dim3 grid(5, 20 * DIMN, 4);        // (w-tiles, h-tiles*d, b)
    elastic_kernel<<<grid, block>>>(x, flow, out);
}